// round 16
// baseline (speedup 1.0000x reference)
#include <cuda_runtime.h>
#include <cstdint>

#define NODES   64
#define NINPUT  16
#define NOUT    8
#define NEDGE   256
#define BATCH   8192
#define PASSES  64
#define G       16            // edge slots per chunk
#define TB      128           // threads per block (4 warps)
#define CPB     16            // columns per block (4 cols per warp via float2)
#define PAIRS   8             // column pairs per block
#define GRIDB   (BATCH / CPB) // 512 blocks
#define RS      88            // float2 rows per pair: 88 = 8 mod 16, so pair B
                              // (lanes 16-31) sits 8 bank-pairs off pair A ->
                              // bin load = mod-8 class count; rows 64..87 are
                              // scratch for class-aware pad slots
#define MAXCH   257           // worst case chunks + wrap chunk

__device__ uint2 g_recs[MAXCH * G + G];
__device__ int   g_nchunks;

// 64-bit inclusive OR-scan across the warp
__device__ __forceinline__ unsigned long long orscan_incl(unsigned long long x,
                                                          int lane) {
    #pragma unroll
    for (int o = 1; o < 32; o <<= 1) {
        unsigned lo = __shfl_up_sync(0xffffffffu, (unsigned)x, o);
        unsigned hi = __shfl_up_sync(0xffffffffu, (unsigned)(x >> 32), o);
        unsigned long long y = ((unsigned long long)hi << 32) | lo;
        if (lane >= o) x |= y;
    }
    return x;
}

__device__ __forceinline__ unsigned long long bcast64(unsigned long long x,
                                                      int srclane) {
    unsigned lo = __shfl_sync(0xffffffffu, (unsigned)x, srclane);
    unsigned hi = __shfl_sync(0xffffffffu, (unsigned)(x >> 32), srclane);
    return ((unsigned long long)hi << 32) | lo;
}

// ---------------------------------------------------------------------------
// Warp-parallel greedy list scheduler (verified R6 dependence rules) + mod-8
// CLASS CAPS: each chunk holds at most 2 member dsts per (dst mod 8) class
// and at most 2 member srcs per (src mod 8) class. With RS = 8 mod 16, this
// caps every LDS.64/STS.64 bank-pair bin at multiplicity 2 = the 2-wavefront
// floor. Cap rejections only DEFER edges (dependence rules unchanged), so
// the schedule remains a legal reordering; >=1 member per chunk guarantees
// progress. Pads are assigned class-aware scratch rows (64+c / 72+c).
// rec.x = (dst_byte_off << 16) | src_byte_off (row stride 8B = float2);
// rec.y = w * 2*log2(e).
// ---------------------------------------------------------------------------
__global__ void sched_kernel(const float* __restrict__ wght,
                             const int*   __restrict__ src,
                             const int*   __restrict__ dst) {
    __shared__ int   ss[NEDGE], sd[NEDGE];
    __shared__ float sw[NEDGE];
    __shared__ short rlist[NEDGE], tmpl[NEDGE];
    __shared__ unsigned char accf[NEDGE];
    const int lane = threadIdx.x;
    const float K2 = 2.8853900817779268f;  // 2 * log2(e)

    for (int e = lane; e < NEDGE; e += 32) {
        ss[e] = src[e]; sd[e] = dst[e]; sw[e] = wght[e] * K2;
        rlist[e] = (short)e;
    }
    __syncwarp();

    const unsigned ltmask = (1u << lane) - 1u;

    int nrem = NEDGE, nch = 0;
    while (nrem > 0) {
        // clear accept flags for every remaining position (scan may early-exit)
        for (int i = lane; i < nrem; i += 32) accf[i] = 0;
        __syncwarp();

        unsigned long long Wall = 0ull, Rall = 0ull, Wmem = 0ull;
        unsigned D1 = 0u, D2 = 0u;   // dst mod-8 class count >=1 / >=2
        unsigned S1 = 0u, S2 = 0u;   // src mod-8 class count >=1 / >=2
        int members = 0;
        for (int base = 0; base < nrem && members < G; base += 32) {
            const int  idx   = base + lane;
            const bool valid = idx < nrem;
            const int  e = valid ? rlist[idx] : 0;
            const int  s = ss[e], d = sd[e];
            const unsigned long long myW = valid ? (1ull << d) : 0ull;
            const unsigned long long myR = valid ? (1ull << s) : 0ull;
            const unsigned long long iW = orscan_incl(myW, lane);
            const unsigned long long iR = orscan_incl(myR, lane);
            unsigned lo = __shfl_up_sync(0xffffffffu, (unsigned)iW, 1);
            unsigned hi = __shfl_up_sync(0xffffffffu, (unsigned)(iW >> 32), 1);
            const unsigned long long eW =
                (lane == 0) ? 0ull : (((unsigned long long)hi << 32) | lo);
            lo = __shfl_up_sync(0xffffffffu, (unsigned)iR, 1);
            hi = __shfl_up_sync(0xffffffffu, (unsigned)(iR >> 32), 1);
            const unsigned long long eR =
                (lane == 0) ? 0ull : (((unsigned long long)hi << 32) | lo);

            const unsigned long long tWall = Wall | eW;  // excl scan, all W
            const unsigned long long tRall = Rall | eR;  // excl scan, all R
            const bool ok0 = valid &&
                             !((tWall >> s) & 1ull) &&
                             !((tRall >> d) & 1ull) &&
                             !((Wmem  >> d) & 1ull);
            // intra-batch member-dst dedup (keep lowest ok0 lane per dst)
            const unsigned peers = __match_any_sync(0xffffffffu, d);
            const unsigned bal0  = __ballot_sync(0xffffffffu, ok0);
            const bool ok = ok0 && ((peers & bal0 & ltmask) == 0u);

            // --- mod-8 class caps ---
            const int dcl = d & 7, scl = s & 7;
            const unsigned dbit = 1u << dcl, sbit = 1u << scl;
            const int capD = (D2 & dbit) ? 0 : ((D1 & dbit) ? 1 : 2);
            const int capS = (S2 & sbit) ? 0 : ((S1 & sbit) ? 1 : 2);
            const bool okA = ok && capD > 0 && capS > 0;
            const unsigned balA = __ballot_sync(0xffffffffu, okA);
            const unsigned pD   = __match_any_sync(0xffffffffu, dcl) & balA;
            const int  rD  = __popc(pD & ltmask);
            const bool okB = okA && rD < capD;
            const unsigned balB = __ballot_sync(0xffffffffu, okB);
            const unsigned pS   = __match_any_sync(0xffffffffu, scl) & balB;
            const int  rS  = __popc(pS & ltmask);
            const bool okC = okB && rS < capS;

            const unsigned bal  = __ballot_sync(0xffffffffu, okC);
            const int      rank = members + __popc(bal & ltmask);
            const bool accept = okC && (rank < G);
            if (accept) {
                uint2 rec;
                rec.x = ((unsigned)(d * 8) << 16) | (unsigned)(s * 8);
                rec.y = __float_as_uint(sw[e]);
                g_recs[nch * G + rank] = rec;
                accf[idx] = 1;
            }
            members += __popc(__ballot_sync(0xffffffffu, accept));
            // fold footprints of everything scanned + member write set
            Wall |= bcast64(iW, 31);
            Rall |= bcast64(iR, 31);
            const unsigned accWlo = __reduce_or_sync(0xffffffffu,
                accept ? (unsigned)(1ull << d) : 0u);
            const unsigned accWhi = __reduce_or_sync(0xffffffffu,
                accept ? (unsigned)((1ull << d) >> 32) : 0u);
            Wmem |= ((unsigned long long)accWhi << 32) | accWlo;
            // class count updates (conservative overcount is safe: only
            // tightens caps / defers edges)
            const unsigned aD0 = __reduce_or_sync(0xffffffffu,
                (accept && rD == 0) ? dbit : 0u);
            const unsigned aD1 = __reduce_or_sync(0xffffffffu,
                (accept && rD >= 1) ? dbit : 0u);
            D2 |= aD1 | (D1 & aD0);
            D1 |= aD0 | aD1;
            const unsigned aS0 = __reduce_or_sync(0xffffffffu,
                (accept && rS == 0) ? sbit : 0u);
            const unsigned aS1 = __reduce_or_sync(0xffffffffu,
                (accept && rS >= 1) ? sbit : 0u);
            S2 |= aS1 | (S1 & aS0);
            S1 |= aS0 | aS1;
        }
        // class-aware pads: scratch rows 64+c (1st pad in class) / 72+c (2nd)
        if (lane == 0) {
            unsigned c1 = D1, c2 = D2;
            for (int j = members; j < G; j++) {
                const unsigned freec = (~c2) & 0xFFu;
                int row;
                if (freec) {
                    const int c = __ffs(freec) - 1;
                    row = (c1 & (1u << c)) ? (72 + c) : (64 + c);
                    if (c1 & (1u << c)) c2 |= 1u << c; else c1 |= 1u << c;
                } else {
                    row = 80 + (j & 7);  // fallback (overcount corner case)
                }
                uint2 rec;
                rec.x = ((unsigned)(row * 8) << 16) | (unsigned)(row * 8);
                rec.y = 0u;              // w=0 -> tanh(0)=0 -> exact no-op
                g_recs[nch * G + j] = rec;
            }
        }
        // compact remaining list (program order preserved)
        int wrpos = 0;
        for (int base = 0; base < nrem; base += 32) {
            const int  idx   = base + lane;
            const bool valid = idx < nrem;
            const int  e     = valid ? rlist[idx] : 0;
            const bool keep  = valid && !accf[idx];
            const unsigned kb = __ballot_sync(0xffffffffu, keep);
            if (keep) tmpl[wrpos + __popc(kb & ltmask)] = (short)e;
            wrpos += __popc(kb);
        }
        __syncwarp();
        for (int i = lane; i < wrpos; i += 32) rlist[i] = tmpl[i];
        __syncwarp();
        nrem = wrpos;
        nch++;
    }
    // wrap chunk = copy of chunk 0 (prefetch wrap-around)
    if (lane < G) g_recs[nch * G + lane] = g_recs[lane];
    if (lane == 0) g_nchunks = nch;
}

// ---------------------------------------------------------------------------
// Main kernel: warp = 2 column-PAIRS x 16 edge slots; each lane handles one
// edge for TWO batch columns via float2 (LDS.64/STS.64). Node state:
// vals[pair][row] as float2, RS=88 rows (64 nodes + 24 scratch). With the
// scheduler's mod-8 class caps every smem access is at the 2-wavefront
// floor. __syncwarp() orders smem between chunks. tanh(x) =
// 1 - 2/(exp2(x*2log2e)+1) via MUFU ex2/rcp (~1e-6 per-op error).
// ---------------------------------------------------------------------------
__global__ void __launch_bounds__(TB, 1)
net_kernel(const float* __restrict__ x, float* __restrict__ out) {
    __shared__ float2 vals[PAIRS * RS];

    const int tid  = threadIdx.x;
    const int lane = tid & 31;
    const int wid  = tid >> 5;
    const int pair = wid * 2 + (lane >> 4);  // local pair 0..7
    const int slot = lane & 15;
    const int bc   = blockIdx.x * CPB;

    float* vf = (float*)vals;
    // inputs rows 0..15
    for (int i = tid; i < CPB * NINPUT; i += TB) {
        const int r = i >> 4, c = i & 15;
        vf[(((c >> 1) * RS) + r) * 2 + (c & 1)] = x[r * BATCH + bc + c];
    }
    // zeros rows 16..87 (nodes + scratch)
    for (int i = tid; i < CPB * (RS - NINPUT); i += TB) {
        const int r = NINPUT + (i >> 4), c = i & 15;
        vf[(((c >> 1) * RS) + r) * 2 + (c & 1)] = 0.0f;
    }
    __syncthreads();

    const int nch = g_nchunks;
    char* base = (char*)(vals + pair * RS);

    uint2 rec = __ldg(&g_recs[slot]);
    #pragma unroll 1
    for (int p = 0; p < PASSES; p++) {
        #pragma unroll 2
        for (int c = 0; c < nch; c++) {
            const uint2 nxt = __ldg(&g_recs[(c + 1) * G + slot]);  // wrap=chunk0
            const unsigned sb = rec.x & 0xffffu;
            const unsigned db = rec.x >> 16;
            const float wv = __uint_as_float(rec.y);
            const float2 v  = *(const float2*)(base + sb);   // src, 2 cols
            const float2 pv = *(const float2*)(base + db);   // dst, 2 cols
            const float a0 = v.x * wv;
            const float a1 = v.y * wv;
            float e0, e1, r0, r1;
            asm("ex2.approx.f32 %0, %1;" : "=f"(e0) : "f"(a0));
            asm("ex2.approx.f32 %0, %1;" : "=f"(e1) : "f"(a1));
            asm("rcp.approx.f32 %0, %1;" : "=f"(r0) : "f"(e0 + 1.0f));
            asm("rcp.approx.f32 %0, %1;" : "=f"(r1) : "f"(e1 + 1.0f));
            float2 res;
            res.x = fmaf(-2.0f, r0, pv.x + 1.0f);  // pv + 1 - 2/(e+1)
            res.y = fmaf(-2.0f, r1, pv.y + 1.0f);
            *(float2*)(base + db) = res;
            rec = nxt;
            __syncwarp();
        }
    }
    __syncthreads();

    for (int i = tid; i < CPB * NOUT; i += TB) {
        const int r = i >> 4, c = i & 15;
        const float vv = vf[(((c >> 1) * RS) + NINPUT + r) * 2 + (c & 1)];
        out[r * BATCH + bc + c] = tanhf(vv);
    }
}

extern "C" void kernel_launch(void* const* d_in, const int* in_sizes, int n_in,
                              void* d_out, int out_size) {
    const float* x   = (const float*)d_in[0];
    const float* w   = (const float*)d_in[1];
    const int*   src = (const int*)d_in[2];
    const int*   dst = (const int*)d_in[3];
    (void)in_sizes; (void)n_in; (void)out_size;

    sched_kernel<<<1, 32>>>(w, src, dst);
    net_kernel<<<GRIDB, TB>>>(x, (float*)d_out);
}

// round 17
// speedup vs baseline: 1.4010x; 1.4010x over previous
#include <cuda_runtime.h>
#include <cstdint>

#define NODES   64
#define NINPUT  16
#define NOUT    8
#define NEDGE   256
#define BATCH   8192
#define PASSES  64
#define G       16            // edge slots per chunk
#define TB      128           // threads per block (4 warps)
#define CPB     16            // columns per block (4 cols per warp via float2)
#define PAIRS   8             // column pairs per block
#define GRIDB   (BATCH / CPB) // 512 blocks
#define RS      65            // float2 rows per pair (64 nodes + scratch 64)
#define MAXCH   257           // worst case chunks + wrap chunk

__device__ uint2 g_recs[MAXCH * G + G];
__device__ int   g_nchunks;

// 64-bit inclusive OR-scan across the warp
__device__ __forceinline__ unsigned long long orscan_incl(unsigned long long x,
                                                          int lane) {
    #pragma unroll
    for (int o = 1; o < 32; o <<= 1) {
        unsigned lo = __shfl_up_sync(0xffffffffu, (unsigned)x, o);
        unsigned hi = __shfl_up_sync(0xffffffffu, (unsigned)(x >> 32), o);
        unsigned long long y = ((unsigned long long)hi << 32) | lo;
        if (lane >= o) x |= y;
    }
    return x;
}

__device__ __forceinline__ unsigned long long bcast64(unsigned long long x,
                                                      int srclane) {
    unsigned lo = __shfl_sync(0xffffffffu, (unsigned)x, srclane);
    unsigned hi = __shfl_sync(0xffffffffu, (unsigned)(x >> 32), srclane);
    return ((unsigned long long)hi << 32) | lo;
}

// ---------------------------------------------------------------------------
// Warp-parallel greedy list scheduler (verified R6 version). Dependence rules
// for the sum-accumulation graph:
//   RAW: candidate src not written by any earlier remaining edge/member
//   WAR: candidate dst not read by any earlier remaining edge/member
//   in-chunk WAW race: member dsts pairwise distinct
//   WAW across chunks: unordered (fp adds commute; reassociation only)
// accf[] zero-filled for all remaining positions each chunk (R5 lesson).
// rec.x = (dst_byte_off << 16) | src_byte_off with row stride 8 bytes
// (float2 node rows); rec.y = w * 2*log2(e).
// ---------------------------------------------------------------------------
__global__ void sched_kernel(const float* __restrict__ wght,
                             const int*   __restrict__ src,
                             const int*   __restrict__ dst) {
    __shared__ int   ss[NEDGE], sd[NEDGE];
    __shared__ float sw[NEDGE];
    __shared__ short rlist[NEDGE], tmpl[NEDGE];
    __shared__ unsigned char accf[NEDGE];
    const int lane = threadIdx.x;
    const float K2 = 2.8853900817779268f;  // 2 * log2(e)

    for (int e = lane; e < NEDGE; e += 32) {
        ss[e] = src[e]; sd[e] = dst[e]; sw[e] = wght[e] * K2;
        rlist[e] = (short)e;
    }
    __syncwarp();

    const unsigned ltmask = (1u << lane) - 1u;
    uint2 dummy; dummy.x = (512u << 16) | 512u;  // scratch row 64 (64*8)
    dummy.y = __float_as_uint(0.0f);             // tanh(0)=0 -> exact no-op

    int nrem = NEDGE, nch = 0;
    while (nrem > 0) {
        // clear accept flags for every remaining position (scan may early-exit)
        for (int i = lane; i < nrem; i += 32) accf[i] = 0;
        __syncwarp();

        unsigned long long Wall = 0ull, Rall = 0ull, Wmem = 0ull;
        int members = 0;
        for (int base = 0; base < nrem && members < G; base += 32) {
            const int  idx   = base + lane;
            const bool valid = idx < nrem;
            const int  e = valid ? rlist[idx] : 0;
            const int  s = ss[e], d = sd[e];
            const unsigned long long myW = valid ? (1ull << d) : 0ull;
            const unsigned long long myR = valid ? (1ull << s) : 0ull;
            const unsigned long long iW = orscan_incl(myW, lane);
            const unsigned long long iR = orscan_incl(myR, lane);
            unsigned lo = __shfl_up_sync(0xffffffffu, (unsigned)iW, 1);
            unsigned hi = __shfl_up_sync(0xffffffffu, (unsigned)(iW >> 32), 1);
            const unsigned long long eW =
                (lane == 0) ? 0ull : (((unsigned long long)hi << 32) | lo);
            lo = __shfl_up_sync(0xffffffffu, (unsigned)iR, 1);
            hi = __shfl_up_sync(0xffffffffu, (unsigned)(iR >> 32), 1);
            const unsigned long long eR =
                (lane == 0) ? 0ull : (((unsigned long long)hi << 32) | lo);

            const unsigned long long tWall = Wall | eW;  // excl scan, all W
            const unsigned long long tRall = Rall | eR;  // excl scan, all R
            const bool ok0 = valid &&
                             !((tWall >> s) & 1ull) &&
                             !((tRall >> d) & 1ull) &&
                             !((Wmem  >> d) & 1ull);
            // intra-batch member-dst dedup (keep lowest ok0 lane per dst)
            const unsigned peers = __match_any_sync(0xffffffffu, d);
            const unsigned bal0  = __ballot_sync(0xffffffffu, ok0);
            const bool ok = ok0 && ((peers & bal0 & ltmask) == 0u);
            const unsigned bal  = __ballot_sync(0xffffffffu, ok);
            const int      rank = members + __popc(bal & ltmask);
            const bool accept = ok && (rank < G);
            if (accept) {
                uint2 rec;
                rec.x = ((unsigned)(d * 8) << 16) | (unsigned)(s * 8);
                rec.y = __float_as_uint(sw[e]);
                g_recs[nch * G + rank] = rec;
                accf[idx] = 1;
            }
            members += __popc(__ballot_sync(0xffffffffu, accept));
            // fold footprints of everything scanned + member write set
            Wall |= bcast64(iW, 31);
            Rall |= bcast64(iR, 31);
            const unsigned accWlo = __reduce_or_sync(0xffffffffu,
                accept ? (unsigned)(1ull << d) : 0u);
            const unsigned accWhi = __reduce_or_sync(0xffffffffu,
                accept ? (unsigned)((1ull << d) >> 32) : 0u);
            Wmem |= ((unsigned long long)accWhi << 32) | accWlo;
        }
        if (lane >= members && lane < G) g_recs[nch * G + lane] = dummy;
        // compact remaining list (program order preserved)
        int wrpos = 0;
        for (int base = 0; base < nrem; base += 32) {
            const int  idx   = base + lane;
            const bool valid = idx < nrem;
            const int  e     = valid ? rlist[idx] : 0;
            const bool keep  = valid && !accf[idx];
            const unsigned kb = __ballot_sync(0xffffffffu, keep);
            if (keep) tmpl[wrpos + __popc(kb & ltmask)] = (short)e;
            wrpos += __popc(kb);
        }
        __syncwarp();
        for (int i = lane; i < wrpos; i += 32) rlist[i] = tmpl[i];
        __syncwarp();
        nrem = wrpos;
        nch++;
    }
    // wrap chunk = copy of chunk 0 (prefetch wrap-around)
    if (lane < G) g_recs[nch * G + lane] = g_recs[lane];
    if (lane == 0) g_nchunks = nch;
}

// ---------------------------------------------------------------------------
// Main kernel: warp = 2 column-PAIRS x 16 edge slots; each lane handles one
// edge for TWO batch columns via float2 (LDS.64/STS.64). Node state:
// vals[pair][row] as float2, row 64 = scratch for dummy slots.
// NO per-chunk __syncwarp (validated in R12 with identical schedule +
// rel_err): the warp is converged (uniform branches only), lanes issue each
// instruction together, and the smem pipe processes a warp's accesses in
// program order -- chunk c's STS is ordered before chunk c+1's LDS. A
// compiler-only memory barrier pins program order at the C++ level.
// tanh(x) = 1 - 2/(exp2(x*2log2e)+1) via MUFU ex2/rcp (~1e-6 per-op error).
// ---------------------------------------------------------------------------
__global__ void __launch_bounds__(TB, 1)
net_kernel(const float* __restrict__ x, float* __restrict__ out) {
    __shared__ float2 vals[PAIRS * RS];

    const int tid  = threadIdx.x;
    const int lane = tid & 31;
    const int wid  = tid >> 5;
    const int pair = wid * 2 + (lane >> 4);  // local pair 0..7
    const int slot = lane & 15;
    const int bc   = blockIdx.x * CPB;

    float* vf = (float*)vals;
    // inputs rows 0..15
    for (int i = tid; i < CPB * NINPUT; i += TB) {
        const int r = i >> 4, c = i & 15;
        vf[(((c >> 1) * RS) + r) * 2 + (c & 1)] = x[r * BATCH + bc + c];
    }
    // zeros rows 16..64
    for (int i = tid; i < CPB * (RS - NINPUT); i += TB) {
        const int r = NINPUT + (i >> 4), c = i & 15;
        vf[(((c >> 1) * RS) + r) * 2 + (c & 1)] = 0.0f;
    }
    __syncthreads();

    const int nch = g_nchunks;
    char* base = (char*)(vals + pair * RS);

    uint2 rec = __ldg(&g_recs[slot]);
    #pragma unroll 1
    for (int p = 0; p < PASSES; p++) {
        #pragma unroll 2
        for (int c = 0; c < nch; c++) {
            const uint2 nxt = __ldg(&g_recs[(c + 1) * G + slot]);  // wrap=chunk0
            const unsigned sb = rec.x & 0xffffu;
            const unsigned db = rec.x >> 16;
            const float wv = __uint_as_float(rec.y);
            const float2 v  = *(const float2*)(base + sb);   // src, 2 cols
            const float2 pv = *(const float2*)(base + db);   // dst, 2 cols
            const float a0 = v.x * wv;
            const float a1 = v.y * wv;
            float e0, e1, r0, r1;
            asm("ex2.approx.f32 %0, %1;" : "=f"(e0) : "f"(a0));
            asm("ex2.approx.f32 %0, %1;" : "=f"(e1) : "f"(a1));
            asm("rcp.approx.f32 %0, %1;" : "=f"(r0) : "f"(e0 + 1.0f));
            asm("rcp.approx.f32 %0, %1;" : "=f"(r1) : "f"(e1 + 1.0f));
            float2 res;
            res.x = fmaf(-2.0f, r0, pv.x + 1.0f);  // pv + 1 - 2/(e+1)
            res.y = fmaf(-2.0f, r1, pv.y + 1.0f);
            *(float2*)(base + db) = res;
            rec = nxt;
            asm volatile("" ::: "memory");  // pin smem program order (compiler)
        }
    }
    __syncthreads();

    for (int i = tid; i < CPB * NOUT; i += TB) {
        const int r = i >> 4, c = i & 15;
        const float vv = vf[(((c >> 1) * RS) + NINPUT + r) * 2 + (c & 1)];
        out[r * BATCH + bc + c] = tanhf(vv);
    }
}

extern "C" void kernel_launch(void* const* d_in, const int* in_sizes, int n_in,
                              void* d_out, int out_size) {
    const float* x   = (const float*)d_in[0];
    const float* w   = (const float*)d_in[1];
    const int*   src = (const int*)d_in[2];
    const int*   dst = (const int*)d_in[3];
    (void)in_sizes; (void)n_in; (void)out_size;

    sched_kernel<<<1, 32>>>(w, src, dst);
    net_kernel<<<GRIDB, TB>>>(x, (float*)d_out);
}